// round 12
// baseline (speedup 1.0000x reference)
#include <cuda_runtime.h>
#include <cuda_bf16.h>
#include <cuda_fp16.h>
#include <cstdint>

#define N_ROWS 16384
#define H_DIM  512
#define D_DIM  256
#define K_CB   4096
#define MARGIN 2.5e-3f
#define CAND_CAP 1024

// -------- scratch (static device arrays; no cudaMalloc allowed) --------
__device__ float          g_X [N_ROWS * D_DIM];     // post-LN activations (fp32)
__device__ __nv_bfloat16  g_Xh[N_ROWS * D_DIM];     // bf16 copy for screen
__device__ __nv_bfloat16  g_Eh[K_CB   * D_DIM];     // bf16 codebook
__device__ float          g_a [N_ROWS];             // fl(sum u^2) per row
__device__ float          g_b [K_CB];               // ||e_k||^2
__device__ unsigned       g_mina[N_ROWS];           // approx row-min d (float bits)
__device__ unsigned       g_cnt [N_ROWS];           // candidate counts
__device__ unsigned       g_cand[(size_t)N_ROWS * CAND_CAP]; // (fp16 s)<<16 | k

// ============================================================================
// Kernel 1: projection GEMM + bias + LayerNorm (fused). NUMERICS FROZEN.
// ============================================================================
__global__ __launch_bounds__(256) void proj_ln_kernel(
    const float* __restrict__ F, const float* __restrict__ Wp,
    const float* __restrict__ bp, const float* __restrict__ gamma,
    const float* __restrict__ beta)
{
    __shared__ float As[32][68];
    __shared__ float Bs[32][260];

    const int tid  = threadIdx.x;
    const int warp = tid >> 5;
    const int lane = tid & 31;
    const int m0   = blockIdx.x * 64;

    float acc[8][8];
#pragma unroll
    for (int i = 0; i < 8; i++)
#pragma unroll
        for (int j = 0; j < 8; j++) acc[i][j] = 0.f;

    for (int k0 = 0; k0 < H_DIM; k0 += 32) {
#pragma unroll
        for (int r = 0; r < 2; r++) {
            int idx = tid + r * 256;
            int row = idx >> 3;
            int kk  = (idx & 7) * 4;
            float4 v = *reinterpret_cast<const float4*>(
                &F[(size_t)(m0 + row) * H_DIM + k0 + kk]);
            As[kk + 0][row] = v.x; As[kk + 1][row] = v.y;
            As[kk + 2][row] = v.z; As[kk + 3][row] = v.w;
        }
#pragma unroll
        for (int r = 0; r < 8; r++) {
            int idx = tid + r * 256;
            int d  = idx >> 3;
            int kk = (idx & 7) * 4;
            float4 v = *reinterpret_cast<const float4*>(
                &Wp[(size_t)d * H_DIM + k0 + kk]);
            Bs[kk + 0][d] = v.x; Bs[kk + 1][d] = v.y;
            Bs[kk + 2][d] = v.z; Bs[kk + 3][d] = v.w;
        }
        __syncthreads();
#pragma unroll
        for (int k = 0; k < 32; k++) {
            float4 a0 = *reinterpret_cast<const float4*>(&As[k][warp * 8]);
            float4 a1 = *reinterpret_cast<const float4*>(&As[k][warp * 8 + 4]);
            float4 b0 = *reinterpret_cast<const float4*>(&Bs[k][lane * 8]);
            float4 b1 = *reinterpret_cast<const float4*>(&Bs[k][lane * 8 + 4]);
            float a[8] = {a0.x, a0.y, a0.z, a0.w, a1.x, a1.y, a1.z, a1.w};
            float b[8] = {b0.x, b0.y, b0.z, b0.w, b1.x, b1.y, b1.z, b1.w};
#pragma unroll
            for (int i = 0; i < 8; i++)
#pragma unroll
                for (int j = 0; j < 8; j++) acc[i][j] = fmaf(a[i], b[j], acc[i][j]);
        }
        __syncthreads();
    }

    float bpv[8], gv[8], bv[8];
#pragma unroll
    for (int j = 0; j < 8; j++) {
        int d = lane * 8 + j;
        bpv[j] = bp[d]; gv[j] = gamma[d]; bv[j] = beta[d];
    }
#pragma unroll
    for (int i = 0; i < 8; i++) {
#pragma unroll
        for (int j = 0; j < 8; j++) acc[i][j] += bpv[j];
        float s = 0.f;
#pragma unroll
        for (int j = 0; j < 8; j++) s += acc[i][j];
#pragma unroll
        for (int o = 16; o > 0; o >>= 1) s += __shfl_xor_sync(0xffffffffu, s, o);
        float mu = s * (1.f / 256.f);
        float ss = 0.f;
#pragma unroll
        for (int j = 0; j < 8; j++) { float d2 = acc[i][j] - mu; ss += d2 * d2; }
#pragma unroll
        for (int o = 16; o > 0; o >>= 1) ss += __shfl_xor_sync(0xffffffffu, ss, o);
        float var = ss * (1.f / 256.f);
        float rs  = rsqrtf(var + 1e-5f);
        int row = m0 + warp * 8 + i;
        float out[8];
#pragma unroll
        for (int j = 0; j < 8; j++)
            out[j] = (acc[i][j] - mu) * rs * gv[j] + bv[j];
        *reinterpret_cast<float4*>(&g_X[(size_t)row * D_DIM + lane * 8]) =
            make_float4(out[0], out[1], out[2], out[3]);
        *reinterpret_cast<float4*>(&g_X[(size_t)row * D_DIM + lane * 8 + 4]) =
            make_float4(out[4], out[5], out[6], out[7]);
        __nv_bfloat162 h[4];
        h[0] = __floats2bfloat162_rn(out[0], out[1]);
        h[1] = __floats2bfloat162_rn(out[2], out[3]);
        h[2] = __floats2bfloat162_rn(out[4], out[5]);
        h[3] = __floats2bfloat162_rn(out[6], out[7]);
        *reinterpret_cast<uint4*>(&g_Xh[(size_t)row * D_DIM + lane * 8]) =
            *reinterpret_cast<uint4*>(h);
    }
}

// ============================================================================
// Kernel 2: per-code ||e||^2 + bf16 conversion.
// ============================================================================
__global__ __launch_bounds__(256) void eb_kernel(const float* __restrict__ emb)
{
    int k    = (blockIdx.x * blockDim.x + threadIdx.x) >> 5;
    int lane = threadIdx.x & 31;
    if (k >= K_CB) return;
    const float* row = emb + (size_t)k * D_DIM;
    float4 v0 = *reinterpret_cast<const float4*>(&row[lane * 8]);
    float4 v1 = *reinterpret_cast<const float4*>(&row[lane * 8 + 4]);
    float s = v0.x * v0.x + v0.y * v0.y + v0.z * v0.z + v0.w * v0.w
            + v1.x * v1.x + v1.y * v1.y + v1.z * v1.z + v1.w * v1.w;
#pragma unroll
    for (int o = 16; o > 0; o >>= 1) s += __shfl_xor_sync(0xffffffffu, s, o);
    if (lane == 0) g_b[k] = s;
    __nv_bfloat162 h[4];
    h[0] = __floats2bfloat162_rn(v0.x, v0.y);
    h[1] = __floats2bfloat162_rn(v0.z, v0.w);
    h[2] = __floats2bfloat162_rn(v1.x, v1.y);
    h[3] = __floats2bfloat162_rn(v1.z, v1.w);
    *reinterpret_cast<uint4*>(&g_Eh[(size_t)k * D_DIM + lane * 8]) =
        *reinterpret_cast<uint4*>(h);
}

// ============================================================================
// Kernel 3: g_a[m] (NUMERICS FROZEN); init g_mina and g_cnt.
// ============================================================================
__global__ __launch_bounds__(256) void a_kernel()
{
    int m = blockIdx.x * blockDim.x + threadIdx.x;
    if (m >= N_ROWS) return;
    const float* row = g_X + (size_t)m * D_DIM;
    float acc = 0.f;
#pragma unroll 8
    for (int d = 0; d < D_DIM; d++) {
        float v = row[d];
        acc = __fadd_rn(acc, __fmul_rn(v, v));
    }
    g_a[m] = acc;
    g_mina[m] = 0x7F800000u;   // +inf
    g_cnt[m]  = 0u;
}

// ============================================================================
// Kernel 4: SCREEN v9 — EXACT round-8 mainloop (direct shared arrays, cp.async
// double buffer, fused enc zero-fill). Epilogue: per-warp 64-col row min via
// quad shuffle (as round 8), then IMMEDIATE candidate emission against that
// warp-local min + MARGIN (superset of the global-min filter; no barrier
// crosses acc liveness). No dense score matrix.
// ============================================================================
__device__ __forceinline__ void mma_bf16(float& d0, float& d1, float& d2, float& d3,
                                         uint32_t a0, uint32_t a1, uint32_t a2, uint32_t a3,
                                         uint32_t b0, uint32_t b1)
{
    asm volatile(
        "mma.sync.aligned.m16n8k16.row.col.f32.bf16.bf16.f32 "
        "{%0,%1,%2,%3}, {%4,%5,%6,%7}, {%8,%9}, {%0,%1,%2,%3};"
        : "+f"(d0), "+f"(d1), "+f"(d2), "+f"(d3)
        : "r"(a0), "r"(a1), "r"(a2), "r"(a3), "r"(b0), "r"(b1));
}

__device__ __forceinline__ void ldsm_x4(uint32_t& r0, uint32_t& r1,
                                        uint32_t& r2, uint32_t& r3,
                                        const __nv_bfloat16* p)
{
    uint32_t addr = (uint32_t)__cvta_generic_to_shared(p);
    asm volatile("ldmatrix.sync.aligned.m8n8.x4.shared.b16 {%0,%1,%2,%3}, [%4];"
                 : "=r"(r0), "=r"(r1), "=r"(r2), "=r"(r3) : "r"(addr));
}

__device__ __forceinline__ void cp16(uint32_t smem_addr, const void* gptr)
{
    asm volatile("cp.async.cg.shared.global [%0], [%1], 16;"
                 :: "r"(smem_addr), "l"(gptr));
}

#define PITCH 40   // 32 + 8 bf16 pad

__global__ __launch_bounds__(256, 2) void screen_kernel(float* __restrict__ enc)
{
    __shared__ __align__(16) __nv_bfloat16 Abuf[2][128 * PITCH];
    __shared__ __align__(16) __nv_bfloat16 Bbuf[2][128 * PITCH];
    __shared__ float aS[128];
    __shared__ float bS[128];
    __shared__ unsigned rowminS[128];

    const int tid  = threadIdx.x;
    const int warp = tid >> 5;
    const int lane = tid & 31;
    const int wm   = warp >> 1;      // 0..3 -> 32 rows each
    const int wn   = warp & 1;       // 0..1 -> 64 cols each
    const int m0   = blockIdx.x * 128;
    const int j0   = blockIdx.y * 128;

    if (tid < 128) {
        aS[tid] = g_a[m0 + tid];
        bS[tid] = g_b[j0 + tid];
        rowminS[tid] = 0x7F800000u;
    }

    const int prow = tid >> 2;        // 0..63
    const int pseg = tid & 3;         // 0..3

    auto prefetch = [&](int buf, int k0) {
#pragma unroll
        for (int r = 0; r < 2; r++) {
            int row = prow + r * 64;
            uint32_t da = (uint32_t)__cvta_generic_to_shared(
                &Abuf[buf][row * PITCH + pseg * 8]);
            cp16(da, &g_Xh[(size_t)(m0 + row) * D_DIM + k0 + pseg * 8]);
            uint32_t db = (uint32_t)__cvta_generic_to_shared(
                &Bbuf[buf][row * PITCH + pseg * 8]);
            cp16(db, &g_Eh[(size_t)(j0 + row) * D_DIM + k0 + pseg * 8]);
        }
        asm volatile("cp.async.commit_group;");
    };

    float acc[2][8][4];
#pragma unroll
    for (int mt = 0; mt < 2; mt++)
#pragma unroll
        for (int nn = 0; nn < 8; nn++)
#pragma unroll
            for (int c = 0; c < 4; c++) acc[mt][nn][c] = 0.f;

    const float4 z4 = make_float4(0.f, 0.f, 0.f, 0.f);

    prefetch(0, 0);

    for (int c = 0; c < 8; c++) {            // 8 chunks of BK=32
        asm volatile("cp.async.wait_group 0;");
        __syncthreads();
        if (c < 7) prefetch((c + 1) & 1, (c + 1) * 32);

        // fused enc zero-fill: 16 columns of this CTA's 128x128 block per chunk
#pragma unroll
        for (int r = 0; r < 2; r++) {
            int i   = tid + r * 256;          // 0..511
            int row = i >> 2;                 // 0..127
            int col = c * 16 + (i & 3) * 4;
            *reinterpret_cast<float4*>(
                &enc[(size_t)(m0 + row) * K_CB + j0 + col]) = z4;
        }

        const __nv_bfloat16* Asm = Abuf[c & 1];
        const __nv_bfloat16* Bsm = Bbuf[c & 1];
#pragma unroll
        for (int ks = 0; ks < 2; ks++) {
            const int krow = ks * 16;
            uint32_t a[2][4], b[4][4];
#pragma unroll
            for (int mt = 0; mt < 2; mt++) {
                const __nv_bfloat16* p =
                    &Asm[(wm * 32 + mt * 16 + (lane & 15)) * PITCH
                         + krow + (lane >> 4) * 8];
                ldsm_x4(a[mt][0], a[mt][1], a[mt][2], a[mt][3], p);
            }
#pragma unroll
            for (int nt = 0; nt < 4; nt++) {
                int nrow = wn * 64 + nt * 16 + (lane & 7) + ((lane >> 4) << 3);
                int kcol = krow + ((lane >> 3) & 1) * 8;
                ldsm_x4(b[nt][0], b[nt][1], b[nt][2], b[nt][3],
                        &Bsm[nrow * PITCH + kcol]);
            }
#pragma unroll
            for (int mt = 0; mt < 2; mt++)
#pragma unroll
                for (int nn = 0; nn < 8; nn++)
                    mma_bf16(acc[mt][nn][0], acc[mt][nn][1],
                             acc[mt][nn][2], acc[mt][nn][3],
                             a[mt][0], a[mt][1], a[mt][2], a[mt][3],
                             b[nn >> 1][(nn & 1) * 2], b[nn >> 1][(nn & 1) * 2 + 1]);
        }
    }

    // epilogue: per-row (warp-local 64-col) min + immediate candidate emission.
#pragma unroll
    for (int mt = 0; mt < 2; mt++) {
#pragma unroll
        for (int half = 0; half < 2; half++) {
            int lrow = wm * 32 + mt * 16 + half * 8 + (lane >> 2);
            int grow = m0 + lrow;
            float av = aS[lrow];
            float dmin = 3.4e38f;
#pragma unroll
            for (int nn = 0; nn < 8; nn++) {
                int lcol = wn * 64 + nn * 8 + (lane & 3) * 2;
                float s0 = bS[lcol]     - 2.f * acc[mt][nn][half * 2 + 0];
                float s1 = bS[lcol + 1] - 2.f * acc[mt][nn][half * 2 + 1];
                dmin = fminf(dmin, fminf(av + s0, av + s1));
            }
            // quad reduce: after xor 1 and xor 2, ALL 4 lanes hold the 64-col min
            dmin = fminf(dmin, __shfl_xor_sync(0xffffffffu, dmin, 1));
            dmin = fminf(dmin, __shfl_xor_sync(0xffffffffu, dmin, 2));
            if ((lane & 3) == 0)
                atomicMin(&rowminS[lrow], __float_as_uint(dmin));
            // emit candidates within MARGIN of the warp-local min (superset)
            float lthr = dmin + MARGIN;
#pragma unroll
            for (int nn = 0; nn < 8; nn++) {
                int lcol = wn * 64 + nn * 8 + (lane & 3) * 2;
                float s0 = bS[lcol]     - 2.f * acc[mt][nn][half * 2 + 0];
                float s1 = bS[lcol + 1] - 2.f * acc[mt][nn][half * 2 + 1];
                if (av + s0 <= lthr) {
                    unsigned pos = atomicAdd(&g_cnt[grow], 1u);
                    if (pos < CAND_CAP)
                        g_cand[(size_t)grow * CAND_CAP + pos] =
                            ((unsigned)__half_as_ushort(__float2half_rn(s0)) << 16)
                            | (unsigned)(j0 + lcol);
                }
                if (av + s1 <= lthr) {
                    unsigned pos = atomicAdd(&g_cnt[grow], 1u);
                    if (pos < CAND_CAP)
                        g_cand[(size_t)grow * CAND_CAP + pos] =
                            ((unsigned)__half_as_ushort(__float2half_rn(s1)) << 16)
                            | (unsigned)(j0 + lcol + 1);
                }
            }
        }
    }
    __syncthreads();
    if (tid < 128) atomicMin(&g_mina[m0 + tid], rowminS[tid]);
}

// ============================================================================
// Kernel 5: SELECT v2 — read per-row candidate list, filter by global
// threshold, exact fp32 rescore (FROZEN semantics + smallest-index
// tie-break), write idx + enc one + quant.
// ============================================================================
__global__ __launch_bounds__(128) void select_kernel(
    const float* __restrict__ emb,
    float* __restrict__ quant, float* __restrict__ idxout,
    float* __restrict__ enc)
{
    __shared__ float uS[D_DIM];
    __shared__ int   cand[256];
    __shared__ int   ncand;
    __shared__ unsigned long long best;
    __shared__ int   winner;

    const int m    = blockIdx.x;
    const int tid  = threadIdx.x;
    const int lane = tid & 31;
    const int warp = tid >> 5;

    if (tid == 0) { ncand = 0; best = 0ull; }
    {
        float2 v = *reinterpret_cast<const float2*>(&g_X[(size_t)m * D_DIM + tid * 2]);
        uS[tid * 2]     = v.x;
        uS[tid * 2 + 1] = v.y;
    }
    const float a   = g_a[m];
    const float thr = __uint_as_float(g_mina[m]) + MARGIN;
    const int   cnt = min((int)g_cnt[m], CAND_CAP);
    __syncthreads();

    // filter candidate list by the global threshold
    const unsigned* crow = &g_cand[(size_t)m * CAND_CAP];
    for (int i = tid; i < cnt; i += 128) {
        unsigned packed = crow[i];
        float s = __half2float(__ushort_as_half((unsigned short)(packed >> 16)));
        if (a + s <= thr) {
            int p = atomicAdd(&ncand, 1);
            if (p < 256) cand[p] = (int)(packed & 0xFFFFu);
        }
    }
    __syncthreads();

    const int nc = min(ncand, 256);
    for (int ci = warp; ci < nc; ci += 4) {
        int k = cand[ci];
        const float* e = emb + (size_t)k * D_DIM;
        float4 u0 = *reinterpret_cast<const float4*>(&uS[lane * 8]);
        float4 u1 = *reinterpret_cast<const float4*>(&uS[lane * 8 + 4]);
        float4 e0 = *reinterpret_cast<const float4*>(&e[lane * 8]);
        float4 e1 = *reinterpret_cast<const float4*>(&e[lane * 8 + 4]);
        float dot = 0.f;
        dot = fmaf(u0.x, e0.x, dot); dot = fmaf(u0.y, e0.y, dot);
        dot = fmaf(u0.z, e0.z, dot); dot = fmaf(u0.w, e0.w, dot);
        dot = fmaf(u1.x, e1.x, dot); dot = fmaf(u1.y, e1.y, dot);
        dot = fmaf(u1.z, e1.z, dot); dot = fmaf(u1.w, e1.w, dot);
#pragma unroll
        for (int o = 16; o > 0; o >>= 1)
            dot = __fadd_rn(dot, __shfl_xor_sync(0xffffffffu, dot, o));
        if (lane == 0) {
            float c  = __fmul_rn(2.0f, dot);
            float dd = __fsub_rn(__fadd_rn(a, g_b[k]), c);
            unsigned u = __float_as_uint(dd);
            unsigned s = (u & 0x80000000u) ? ~u : (u | 0x80000000u);
            unsigned long long packed =
                ((unsigned long long)(~s) << 32) | (unsigned)(~(unsigned)k);
            atomicMax(&best, packed);
        }
    }
    __syncthreads();
    if (tid == 0) {
        int k = (int)(~(unsigned)(best & 0xffffffffull));
        winner = k;
        idxout[m] = (float)k;
        enc[(size_t)m * K_CB + k] = 1.0f;
    }
    __syncthreads();
    const int k = winner;
    if (tid < 64) {
        *reinterpret_cast<float4*>(&quant[(size_t)m * D_DIM + tid * 4]) =
            *reinterpret_cast<const float4*>(&emb[(size_t)k * D_DIM + tid * 4]);
    }
}

// ============================================================================
extern "C" void kernel_launch(void* const* d_in, const int* in_sizes, int n_in,
                              void* d_out, int out_size)
{
    const float* F     = (const float*)d_in[0];
    const float* Wp    = (const float*)d_in[1];
    const float* bp    = (const float*)d_in[2];
    const float* gamma = (const float*)d_in[3];
    const float* beta  = (const float*)d_in[4];
    const float* emb   = (const float*)d_in[5];

    float* out    = (float*)d_out;
    float* quant  = out;
    float* idxout = out + (size_t)N_ROWS * D_DIM;
    float* enc    = idxout + N_ROWS;

    proj_ln_kernel<<<N_ROWS / 64, 256>>>(F, Wp, bp, gamma, beta);
    eb_kernel<<<(K_CB * 32) / 256, 256>>>(emb);
    a_kernel<<<N_ROWS / 256, 256>>>();
    screen_kernel<<<dim3(N_ROWS / 128, K_CB / 128), 256>>>(enc);
    select_kernel<<<N_ROWS, 128>>>(emb, quant, idxout, enc);
}

// round 13
// speedup vs baseline: 1.4351x; 1.4351x over previous
#include <cuda_runtime.h>
#include <cuda_bf16.h>
#include <cuda_fp16.h>
#include <cstdint>

#define N_ROWS 16384
#define H_DIM  512
#define D_DIM  256
#define K_CB   4096
#define MARGIN 2.5e-3f

// -------- scratch (static device arrays; no cudaMalloc allowed) --------
__device__ float          g_X [N_ROWS * D_DIM];     // post-LN activations (fp32)
__device__ __nv_bfloat16  g_Xh[N_ROWS * D_DIM];     // bf16 copy for screen
__device__ __nv_bfloat16  g_Eh[K_CB   * D_DIM];     // bf16 codebook
__device__ float          g_a [N_ROWS];             // fl(sum u^2) per row
__device__ float          g_b [K_CB];               // ||e_k||^2
__device__ unsigned       g_mina[N_ROWS];           // approx row-min d (float bits)
__device__ __half         g_Sh[(size_t)N_ROWS * K_CB]; // s = b - 2*dot (fp16)

// ============================================================================
// Kernel 1: projection GEMM + bias + LayerNorm (fused). NUMERICS FROZEN.
// ============================================================================
__global__ __launch_bounds__(256) void proj_ln_kernel(
    const float* __restrict__ F, const float* __restrict__ Wp,
    const float* __restrict__ bp, const float* __restrict__ gamma,
    const float* __restrict__ beta)
{
    __shared__ float As[32][68];
    __shared__ float Bs[32][260];

    const int tid  = threadIdx.x;
    const int warp = tid >> 5;
    const int lane = tid & 31;
    const int m0   = blockIdx.x * 64;

    float acc[8][8];
#pragma unroll
    for (int i = 0; i < 8; i++)
#pragma unroll
        for (int j = 0; j < 8; j++) acc[i][j] = 0.f;

    for (int k0 = 0; k0 < H_DIM; k0 += 32) {
#pragma unroll
        for (int r = 0; r < 2; r++) {
            int idx = tid + r * 256;
            int row = idx >> 3;
            int kk  = (idx & 7) * 4;
            float4 v = *reinterpret_cast<const float4*>(
                &F[(size_t)(m0 + row) * H_DIM + k0 + kk]);
            As[kk + 0][row] = v.x; As[kk + 1][row] = v.y;
            As[kk + 2][row] = v.z; As[kk + 3][row] = v.w;
        }
#pragma unroll
        for (int r = 0; r < 8; r++) {
            int idx = tid + r * 256;
            int d  = idx >> 3;
            int kk = (idx & 7) * 4;
            float4 v = *reinterpret_cast<const float4*>(
                &Wp[(size_t)d * H_DIM + k0 + kk]);
            Bs[kk + 0][d] = v.x; Bs[kk + 1][d] = v.y;
            Bs[kk + 2][d] = v.z; Bs[kk + 3][d] = v.w;
        }
        __syncthreads();
#pragma unroll
        for (int k = 0; k < 32; k++) {
            float4 a0 = *reinterpret_cast<const float4*>(&As[k][warp * 8]);
            float4 a1 = *reinterpret_cast<const float4*>(&As[k][warp * 8 + 4]);
            float4 b0 = *reinterpret_cast<const float4*>(&Bs[k][lane * 8]);
            float4 b1 = *reinterpret_cast<const float4*>(&Bs[k][lane * 8 + 4]);
            float a[8] = {a0.x, a0.y, a0.z, a0.w, a1.x, a1.y, a1.z, a1.w};
            float b[8] = {b0.x, b0.y, b0.z, b0.w, b1.x, b1.y, b1.z, b1.w};
#pragma unroll
            for (int i = 0; i < 8; i++)
#pragma unroll
                for (int j = 0; j < 8; j++) acc[i][j] = fmaf(a[i], b[j], acc[i][j]);
        }
        __syncthreads();
    }

    float bpv[8], gv[8], bv[8];
#pragma unroll
    for (int j = 0; j < 8; j++) {
        int d = lane * 8 + j;
        bpv[j] = bp[d]; gv[j] = gamma[d]; bv[j] = beta[d];
    }
#pragma unroll
    for (int i = 0; i < 8; i++) {
#pragma unroll
        for (int j = 0; j < 8; j++) acc[i][j] += bpv[j];
        float s = 0.f;
#pragma unroll
        for (int j = 0; j < 8; j++) s += acc[i][j];
#pragma unroll
        for (int o = 16; o > 0; o >>= 1) s += __shfl_xor_sync(0xffffffffu, s, o);
        float mu = s * (1.f / 256.f);
        float ss = 0.f;
#pragma unroll
        for (int j = 0; j < 8; j++) { float d2 = acc[i][j] - mu; ss += d2 * d2; }
#pragma unroll
        for (int o = 16; o > 0; o >>= 1) ss += __shfl_xor_sync(0xffffffffu, ss, o);
        float var = ss * (1.f / 256.f);
        float rs  = rsqrtf(var + 1e-5f);
        int row = m0 + warp * 8 + i;
        float out[8];
#pragma unroll
        for (int j = 0; j < 8; j++)
            out[j] = (acc[i][j] - mu) * rs * gv[j] + bv[j];
        *reinterpret_cast<float4*>(&g_X[(size_t)row * D_DIM + lane * 8]) =
            make_float4(out[0], out[1], out[2], out[3]);
        *reinterpret_cast<float4*>(&g_X[(size_t)row * D_DIM + lane * 8 + 4]) =
            make_float4(out[4], out[5], out[6], out[7]);
        __nv_bfloat162 h[4];
        h[0] = __floats2bfloat162_rn(out[0], out[1]);
        h[1] = __floats2bfloat162_rn(out[2], out[3]);
        h[2] = __floats2bfloat162_rn(out[4], out[5]);
        h[3] = __floats2bfloat162_rn(out[6], out[7]);
        *reinterpret_cast<uint4*>(&g_Xh[(size_t)row * D_DIM + lane * 8]) =
            *reinterpret_cast<uint4*>(h);
    }
}

// ============================================================================
// Kernel 2: per-code ||e||^2 + bf16 conversion.
// ============================================================================
__global__ __launch_bounds__(256) void eb_kernel(const float* __restrict__ emb)
{
    int k    = (blockIdx.x * blockDim.x + threadIdx.x) >> 5;
    int lane = threadIdx.x & 31;
    if (k >= K_CB) return;
    const float* row = emb + (size_t)k * D_DIM;
    float4 v0 = *reinterpret_cast<const float4*>(&row[lane * 8]);
    float4 v1 = *reinterpret_cast<const float4*>(&row[lane * 8 + 4]);
    float s = v0.x * v0.x + v0.y * v0.y + v0.z * v0.z + v0.w * v0.w
            + v1.x * v1.x + v1.y * v1.y + v1.z * v1.z + v1.w * v1.w;
#pragma unroll
    for (int o = 16; o > 0; o >>= 1) s += __shfl_xor_sync(0xffffffffu, s, o);
    if (lane == 0) g_b[k] = s;
    __nv_bfloat162 h[4];
    h[0] = __floats2bfloat162_rn(v0.x, v0.y);
    h[1] = __floats2bfloat162_rn(v0.z, v0.w);
    h[2] = __floats2bfloat162_rn(v1.x, v1.y);
    h[3] = __floats2bfloat162_rn(v1.z, v1.w);
    *reinterpret_cast<uint4*>(&g_Eh[(size_t)k * D_DIM + lane * 8]) =
        *reinterpret_cast<uint4*>(h);
}

// ============================================================================
// Kernel 3: g_a[m] (NUMERICS FROZEN); init g_mina.
// ============================================================================
__global__ __launch_bounds__(256) void a_kernel()
{
    int m = blockIdx.x * blockDim.x + threadIdx.x;
    if (m >= N_ROWS) return;
    const float* row = g_X + (size_t)m * D_DIM;
    float acc = 0.f;
#pragma unroll 8
    for (int d = 0; d < D_DIM; d++) {
        float v = row[d];
        acc = __fadd_rn(acc, __fmul_rn(v, v));
    }
    g_a[m] = acc;
    g_mina[m] = 0x7F800000u;   // +inf
}

// ============================================================================
// Kernel 4: SCREEN — EXACT round-8 kernel (185us, rel_err 0.0): bf16 mma.sync
// + cp.async double buffer, one sync per chunk, fused enc zero-fill, dense
// fp16 g_Sh store, per-row min via quad shuffle + smem atomicMin.
// ============================================================================
__device__ __forceinline__ void mma_bf16(float& d0, float& d1, float& d2, float& d3,
                                         uint32_t a0, uint32_t a1, uint32_t a2, uint32_t a3,
                                         uint32_t b0, uint32_t b1)
{
    asm volatile(
        "mma.sync.aligned.m16n8k16.row.col.f32.bf16.bf16.f32 "
        "{%0,%1,%2,%3}, {%4,%5,%6,%7}, {%8,%9}, {%0,%1,%2,%3};"
        : "+f"(d0), "+f"(d1), "+f"(d2), "+f"(d3)
        : "r"(a0), "r"(a1), "r"(a2), "r"(a3), "r"(b0), "r"(b1));
}

__device__ __forceinline__ void ldsm_x4(uint32_t& r0, uint32_t& r1,
                                        uint32_t& r2, uint32_t& r3,
                                        const __nv_bfloat16* p)
{
    uint32_t addr = (uint32_t)__cvta_generic_to_shared(p);
    asm volatile("ldmatrix.sync.aligned.m8n8.x4.shared.b16 {%0,%1,%2,%3}, [%4];"
                 : "=r"(r0), "=r"(r1), "=r"(r2), "=r"(r3) : "r"(addr));
}

__device__ __forceinline__ void cp16(uint32_t smem_addr, const void* gptr)
{
    asm volatile("cp.async.cg.shared.global [%0], [%1], 16;"
                 :: "r"(smem_addr), "l"(gptr));
}

#define PITCH 40   // 32 + 8 bf16 pad

__global__ __launch_bounds__(256) void screen_kernel(float* __restrict__ enc)
{
    __shared__ __align__(16) __nv_bfloat16 Abuf[2][128 * PITCH];
    __shared__ __align__(16) __nv_bfloat16 Bbuf[2][128 * PITCH];
    __shared__ float aS[128];
    __shared__ float bS[128];
    __shared__ unsigned rowminS[128];

    const int tid  = threadIdx.x;
    const int warp = tid >> 5;
    const int lane = tid & 31;
    const int wm   = warp >> 1;      // 0..3 -> 32 rows each
    const int wn   = warp & 1;       // 0..1 -> 64 cols each
    const int m0   = blockIdx.x * 128;
    const int j0   = blockIdx.y * 128;

    if (tid < 128) {
        aS[tid] = g_a[m0 + tid];
        bS[tid] = g_b[j0 + tid];
        rowminS[tid] = 0x7F800000u;
    }

    const int prow = tid >> 2;        // 0..63
    const int pseg = tid & 3;         // 0..3

    auto prefetch = [&](int buf, int k0) {
#pragma unroll
        for (int r = 0; r < 2; r++) {
            int row = prow + r * 64;
            uint32_t da = (uint32_t)__cvta_generic_to_shared(
                &Abuf[buf][row * PITCH + pseg * 8]);
            cp16(da, &g_Xh[(size_t)(m0 + row) * D_DIM + k0 + pseg * 8]);
            uint32_t db = (uint32_t)__cvta_generic_to_shared(
                &Bbuf[buf][row * PITCH + pseg * 8]);
            cp16(db, &g_Eh[(size_t)(j0 + row) * D_DIM + k0 + pseg * 8]);
        }
        asm volatile("cp.async.commit_group;");
    };

    float acc[2][8][4];
#pragma unroll
    for (int mt = 0; mt < 2; mt++)
#pragma unroll
        for (int nn = 0; nn < 8; nn++)
#pragma unroll
            for (int c = 0; c < 4; c++) acc[mt][nn][c] = 0.f;

    const float4 z4 = make_float4(0.f, 0.f, 0.f, 0.f);

    prefetch(0, 0);

    for (int c = 0; c < 8; c++) {            // 8 chunks of BK=32
        asm volatile("cp.async.wait_group 0;");
        __syncthreads();
        if (c < 7) prefetch((c + 1) & 1, (c + 1) * 32);

        // fused enc zero-fill: 16 columns of this CTA's 128x128 block per chunk
#pragma unroll
        for (int r = 0; r < 2; r++) {
            int i   = tid + r * 256;          // 0..511
            int row = i >> 2;                 // 0..127
            int col = c * 16 + (i & 3) * 4;
            *reinterpret_cast<float4*>(
                &enc[(size_t)(m0 + row) * K_CB + j0 + col]) = z4;
        }

        const __nv_bfloat16* Asm = Abuf[c & 1];
        const __nv_bfloat16* Bsm = Bbuf[c & 1];
#pragma unroll
        for (int ks = 0; ks < 2; ks++) {
            const int krow = ks * 16;
            uint32_t a[2][4], b[4][4];
#pragma unroll
            for (int mt = 0; mt < 2; mt++) {
                const __nv_bfloat16* p =
                    &Asm[(wm * 32 + mt * 16 + (lane & 15)) * PITCH
                         + krow + (lane >> 4) * 8];
                ldsm_x4(a[mt][0], a[mt][1], a[mt][2], a[mt][3], p);
            }
#pragma unroll
            for (int nt = 0; nt < 4; nt++) {
                int nrow = wn * 64 + nt * 16 + (lane & 7) + ((lane >> 4) << 3);
                int kcol = krow + ((lane >> 3) & 1) * 8;
                ldsm_x4(b[nt][0], b[nt][1], b[nt][2], b[nt][3],
                        &Bsm[nrow * PITCH + kcol]);
            }
#pragma unroll
            for (int mt = 0; mt < 2; mt++)
#pragma unroll
                for (int nn = 0; nn < 8; nn++)
                    mma_bf16(acc[mt][nn][0], acc[mt][nn][1],
                             acc[mt][nn][2], acc[mt][nn][3],
                             a[mt][0], a[mt][1], a[mt][2], a[mt][3],
                             b[nn >> 1][(nn & 1) * 2], b[nn >> 1][(nn & 1) * 2 + 1]);
        }
    }

    // epilogue: store s = b - 2*dot (fp16); track per-row approx-min of a+s
#pragma unroll
    for (int mt = 0; mt < 2; mt++) {
#pragma unroll
        for (int half = 0; half < 2; half++) {
            int lrow = wm * 32 + mt * 16 + half * 8 + (lane >> 2);
            int grow = m0 + lrow;
            float av = aS[lrow];
            float dmin = 3.4e38f;
#pragma unroll
            for (int nn = 0; nn < 8; nn++) {
                int lcol = wn * 64 + nn * 8 + (lane & 3) * 2;
                float s0 = bS[lcol]     - 2.f * acc[mt][nn][half * 2 + 0];
                float s1 = bS[lcol + 1] - 2.f * acc[mt][nn][half * 2 + 1];
                __half2 h = __floats2half2_rn(s0, s1);
                *reinterpret_cast<__half2*>(&g_Sh[(size_t)grow * K_CB + j0 + lcol]) = h;
                dmin = fminf(dmin, fminf(av + s0, av + s1));
            }
            dmin = fminf(dmin, __shfl_xor_sync(0xffffffffu, dmin, 1));
            dmin = fminf(dmin, __shfl_xor_sync(0xffffffffu, dmin, 2));
            if ((lane & 3) == 0)
                atomicMin(&rowminS[lrow], __float_as_uint(dmin));
        }
    }
    __syncthreads();
    if (tid < 128) atomicMin(&g_mina[m0 + tid], rowminS[tid]);
}

// ============================================================================
// Kernel 5: SELECT — 256 threads/row (widened from 128): scan fp16 s row,
// candidates within MARGIN of approx min, exact fp32 rescore (FROZEN
// semantics + smallest-index tie-break; order-invariant packed atomicMax).
// ============================================================================
__global__ __launch_bounds__(256) void select_kernel(
    const float* __restrict__ emb,
    float* __restrict__ quant, float* __restrict__ idxout,
    float* __restrict__ enc)
{
    __shared__ float uS[D_DIM];
    __shared__ int   cand[1024];
    __shared__ int   ncand;
    __shared__ unsigned long long best;
    __shared__ int   winner;

    const int m    = blockIdx.x;
    const int tid  = threadIdx.x;
    const int lane = tid & 31;
    const int warp = tid >> 5;

    if (tid == 0) { ncand = 0; best = 0ull; }
    uS[tid] = g_X[(size_t)m * D_DIM + tid];          // 256 threads, 1 float each
    const float a   = g_a[m];
    const float thr = __uint_as_float(g_mina[m]) + MARGIN;
    __syncthreads();

    const __half* srow = &g_Sh[(size_t)m * K_CB];
#pragma unroll
    for (int base = 0; base < K_CB; base += 2048) {  // 2 iterations
        int idx = base + tid * 8;
        uint4 raw = *reinterpret_cast<const uint4*>(&srow[idx]);
        const uint32_t rw[4] = {raw.x, raw.y, raw.z, raw.w};
#pragma unroll
        for (int q = 0; q < 4; q++) {
            __half2 h = *reinterpret_cast<const __half2*>(&rw[q]);
            float2 s2 = __half22float2(h);
            float d0 = a + s2.x, d1 = a + s2.y;
            if (d0 <= thr) { int p = atomicAdd(&ncand, 1); if (p < 1024) cand[p] = idx + q * 2; }
            if (d1 <= thr) { int p = atomicAdd(&ncand, 1); if (p < 1024) cand[p] = idx + q * 2 + 1; }
        }
    }
    __syncthreads();

    const int nc = min(ncand, 1024);
    for (int ci = warp; ci < nc; ci += 8) {          // 8 warps
        int k = cand[ci];
        const float* e = emb + (size_t)k * D_DIM;
        float4 u0 = *reinterpret_cast<const float4*>(&uS[lane * 8]);
        float4 u1 = *reinterpret_cast<const float4*>(&uS[lane * 8 + 4]);
        float4 e0 = *reinterpret_cast<const float4*>(&e[lane * 8]);
        float4 e1 = *reinterpret_cast<const float4*>(&e[lane * 8 + 4]);
        float dot = 0.f;
        dot = fmaf(u0.x, e0.x, dot); dot = fmaf(u0.y, e0.y, dot);
        dot = fmaf(u0.z, e0.z, dot); dot = fmaf(u0.w, e0.w, dot);
        dot = fmaf(u1.x, e1.x, dot); dot = fmaf(u1.y, e1.y, dot);
        dot = fmaf(u1.z, e1.z, dot); dot = fmaf(u1.w, e1.w, dot);
#pragma unroll
        for (int o = 16; o > 0; o >>= 1)
            dot = __fadd_rn(dot, __shfl_xor_sync(0xffffffffu, dot, o));
        if (lane == 0) {
            float c  = __fmul_rn(2.0f, dot);
            float dd = __fsub_rn(__fadd_rn(a, g_b[k]), c);
            unsigned u = __float_as_uint(dd);
            unsigned s = (u & 0x80000000u) ? ~u : (u | 0x80000000u);
            unsigned long long packed =
                ((unsigned long long)(~s) << 32) | (unsigned)(~(unsigned)k);
            atomicMax(&best, packed);
        }
    }
    __syncthreads();
    if (tid == 0) {
        int k = (int)(~(unsigned)(best & 0xffffffffull));
        winner = k;
        idxout[m] = (float)k;
        enc[(size_t)m * K_CB + k] = 1.0f;
    }
    __syncthreads();
    const int k = winner;
    if (tid < 64) {
        *reinterpret_cast<float4*>(&quant[(size_t)m * D_DIM + tid * 4]) =
            *reinterpret_cast<const float4*>(&emb[(size_t)k * D_DIM + tid * 4]);
    }
}

// ============================================================================
extern "C" void kernel_launch(void* const* d_in, const int* in_sizes, int n_in,
                              void* d_out, int out_size)
{
    const float* F     = (const float*)d_in[0];
    const float* Wp    = (const float*)d_in[1];
    const float* bp    = (const float*)d_in[2];
    const float* gamma = (const float*)d_in[3];
    const float* beta  = (const float*)d_in[4];
    const float* emb   = (const float*)d_in[5];

    float* out    = (float*)d_out;
    float* quant  = out;
    float* idxout = out + (size_t)N_ROWS * D_DIM;
    float* enc    = idxout + N_ROWS;

    proj_ln_kernel<<<N_ROWS / 64, 256>>>(F, Wp, bp, gamma, beta);
    eb_kernel<<<(K_CB * 32) / 256, 256>>>(emb);
    a_kernel<<<N_ROWS / 256, 256>>>();
    screen_kernel<<<dim3(N_ROWS / 128, K_CB / 128), 256>>>(enc);
    select_kernel<<<N_ROWS, 256>>>(emb, quant, idxout, enc);
}

// round 14
// speedup vs baseline: 1.4973x; 1.0433x over previous
#include <cuda_runtime.h>
#include <cuda_bf16.h>
#include <cuda_fp16.h>
#include <cstdint>

#define N_ROWS 16384
#define H_DIM  512
#define D_DIM  256
#define K_CB   4096
#define MARGIN 2.5e-3f

// -------- scratch (static device arrays; no cudaMalloc allowed) --------
__device__ float          g_X [N_ROWS * D_DIM];     // post-LN activations (fp32)
__device__ __nv_bfloat16  g_Xh[N_ROWS * D_DIM];     // bf16 copy for screen
__device__ __nv_bfloat16  g_Eh[K_CB   * D_DIM];     // bf16 codebook
__device__ float          g_a [N_ROWS];             // fl(sum u^2) per row
__device__ float          g_b [K_CB];               // ||e_k||^2
__device__ unsigned       g_mina[N_ROWS];           // approx row-min d (float bits)
__device__ __half         g_Sh[(size_t)N_ROWS * K_CB]; // s = b - 2*dot (fp16)

// ============================================================================
// Kernel 1: projection GEMM + bias + LayerNorm (fused).
// v2: BK=16, double-buffered smem, register prefetch, ONE sync per chunk.
// FMA accumulation order is UNCHANGED (k ascends 0..511 per thread) -> the
// produced g_X / g_Xh values are bit-identical to the validated kernel.
// ============================================================================
__global__ __launch_bounds__(256, 2) void proj_ln_kernel(
    const float* __restrict__ F, const float* __restrict__ Wp,
    const float* __restrict__ bp, const float* __restrict__ gamma,
    const float* __restrict__ beta)
{
    __shared__ float As[2][16][68];    // [buf][k][m], padded
    __shared__ float Bs[2][16][260];   // [buf][k][d], padded

    const int tid  = threadIdx.x;
    const int warp = tid >> 5;
    const int lane = tid & 31;
    const int m0   = blockIdx.x * 64;

    // per-thread load coords (1 float4 for A, 4 for B, per chunk)
    const int arow = tid >> 2;            // 0..63
    const int akk  = (tid & 3) * 4;       // 0,4,8,12

    float acc[8][8];
#pragma unroll
    for (int i = 0; i < 8; i++)
#pragma unroll
        for (int j = 0; j < 8; j++) acc[i][j] = 0.f;

    // prologue: chunk 0 direct to buffer 0
    {
        float4 v = *reinterpret_cast<const float4*>(
            &F[(size_t)(m0 + arow) * H_DIM + akk]);
        As[0][akk + 0][arow] = v.x; As[0][akk + 1][arow] = v.y;
        As[0][akk + 2][arow] = v.z; As[0][akk + 3][arow] = v.w;
#pragma unroll
        for (int r = 0; r < 4; r++) {
            int idx = tid + r * 256;
            int d  = idx >> 2;
            int kk = (idx & 3) * 4;
            float4 w = *reinterpret_cast<const float4*>(
                &Wp[(size_t)d * H_DIM + kk]);
            Bs[0][kk + 0][d] = w.x; Bs[0][kk + 1][d] = w.y;
            Bs[0][kk + 2][d] = w.z; Bs[0][kk + 3][d] = w.w;
        }
    }
    __syncthreads();

    for (int c = 0; c < 32; c++) {        // 32 chunks of BK=16
        const int cur = c & 1;
        const int nxt = cur ^ 1;
        // prefetch chunk c+1 into registers (latency overlaps compute)
        float4 pa;
        float4 pb0, pb1, pb2, pb3;
        if (c < 31) {
            const int k0 = (c + 1) * 16;
            pa = *reinterpret_cast<const float4*>(
                &F[(size_t)(m0 + arow) * H_DIM + k0 + akk]);
            {
                int idx = tid;
                pb0 = *reinterpret_cast<const float4*>(
                    &Wp[(size_t)(idx >> 2) * H_DIM + k0 + (idx & 3) * 4]);
                idx = tid + 256;
                pb1 = *reinterpret_cast<const float4*>(
                    &Wp[(size_t)(idx >> 2) * H_DIM + k0 + (idx & 3) * 4]);
                idx = tid + 512;
                pb2 = *reinterpret_cast<const float4*>(
                    &Wp[(size_t)(idx >> 2) * H_DIM + k0 + (idx & 3) * 4]);
                idx = tid + 768;
                pb3 = *reinterpret_cast<const float4*>(
                    &Wp[(size_t)(idx >> 2) * H_DIM + k0 + (idx & 3) * 4]);
            }
        }
#pragma unroll
        for (int k = 0; k < 16; k++) {
            float4 a0 = *reinterpret_cast<const float4*>(&As[cur][k][warp * 8]);
            float4 a1 = *reinterpret_cast<const float4*>(&As[cur][k][warp * 8 + 4]);
            float4 b0 = *reinterpret_cast<const float4*>(&Bs[cur][k][lane * 8]);
            float4 b1 = *reinterpret_cast<const float4*>(&Bs[cur][k][lane * 8 + 4]);
            float a[8] = {a0.x, a0.y, a0.z, a0.w, a1.x, a1.y, a1.z, a1.w};
            float b[8] = {b0.x, b0.y, b0.z, b0.w, b1.x, b1.y, b1.z, b1.w};
#pragma unroll
            for (int i = 0; i < 8; i++)
#pragma unroll
                for (int j = 0; j < 8; j++) acc[i][j] = fmaf(a[i], b[j], acc[i][j]);
        }
        if (c < 31) {
            As[nxt][akk + 0][arow] = pa.x; As[nxt][akk + 1][arow] = pa.y;
            As[nxt][akk + 2][arow] = pa.z; As[nxt][akk + 3][arow] = pa.w;
            {
                int idx = tid;
                Bs[nxt][(idx & 3) * 4 + 0][idx >> 2] = pb0.x;
                Bs[nxt][(idx & 3) * 4 + 1][idx >> 2] = pb0.y;
                Bs[nxt][(idx & 3) * 4 + 2][idx >> 2] = pb0.z;
                Bs[nxt][(idx & 3) * 4 + 3][idx >> 2] = pb0.w;
                idx = tid + 256;
                Bs[nxt][(idx & 3) * 4 + 0][idx >> 2] = pb1.x;
                Bs[nxt][(idx & 3) * 4 + 1][idx >> 2] = pb1.y;
                Bs[nxt][(idx & 3) * 4 + 2][idx >> 2] = pb1.z;
                Bs[nxt][(idx & 3) * 4 + 3][idx >> 2] = pb1.w;
                idx = tid + 512;
                Bs[nxt][(idx & 3) * 4 + 0][idx >> 2] = pb2.x;
                Bs[nxt][(idx & 3) * 4 + 1][idx >> 2] = pb2.y;
                Bs[nxt][(idx & 3) * 4 + 2][idx >> 2] = pb2.z;
                Bs[nxt][(idx & 3) * 4 + 3][idx >> 2] = pb2.w;
                idx = tid + 768;
                Bs[nxt][(idx & 3) * 4 + 0][idx >> 2] = pb3.x;
                Bs[nxt][(idx & 3) * 4 + 1][idx >> 2] = pb3.y;
                Bs[nxt][(idx & 3) * 4 + 2][idx >> 2] = pb3.z;
                Bs[nxt][(idx & 3) * 4 + 3][idx >> 2] = pb3.w;
            }
        }
        __syncthreads();
    }

    // epilogue: +bp, LayerNorm over 256 cols of each row, write g_X (FROZEN)
    float bpv[8], gv[8], bv[8];
#pragma unroll
    for (int j = 0; j < 8; j++) {
        int d = lane * 8 + j;
        bpv[j] = bp[d]; gv[j] = gamma[d]; bv[j] = beta[d];
    }
#pragma unroll
    for (int i = 0; i < 8; i++) {
#pragma unroll
        for (int j = 0; j < 8; j++) acc[i][j] += bpv[j];
        float s = 0.f;
#pragma unroll
        for (int j = 0; j < 8; j++) s += acc[i][j];
#pragma unroll
        for (int o = 16; o > 0; o >>= 1) s += __shfl_xor_sync(0xffffffffu, s, o);
        float mu = s * (1.f / 256.f);
        float ss = 0.f;
#pragma unroll
        for (int j = 0; j < 8; j++) { float d2 = acc[i][j] - mu; ss += d2 * d2; }
#pragma unroll
        for (int o = 16; o > 0; o >>= 1) ss += __shfl_xor_sync(0xffffffffu, ss, o);
        float var = ss * (1.f / 256.f);
        float rs  = rsqrtf(var + 1e-5f);
        int row = m0 + warp * 8 + i;
        float out[8];
#pragma unroll
        for (int j = 0; j < 8; j++)
            out[j] = (acc[i][j] - mu) * rs * gv[j] + bv[j];
        *reinterpret_cast<float4*>(&g_X[(size_t)row * D_DIM + lane * 8]) =
            make_float4(out[0], out[1], out[2], out[3]);
        *reinterpret_cast<float4*>(&g_X[(size_t)row * D_DIM + lane * 8 + 4]) =
            make_float4(out[4], out[5], out[6], out[7]);
        __nv_bfloat162 h[4];
        h[0] = __floats2bfloat162_rn(out[0], out[1]);
        h[1] = __floats2bfloat162_rn(out[2], out[3]);
        h[2] = __floats2bfloat162_rn(out[4], out[5]);
        h[3] = __floats2bfloat162_rn(out[6], out[7]);
        *reinterpret_cast<uint4*>(&g_Xh[(size_t)row * D_DIM + lane * 8]) =
            *reinterpret_cast<uint4*>(h);
    }
}

// ============================================================================
// Kernel 2: per-code ||e||^2 + bf16 conversion.
// ============================================================================
__global__ __launch_bounds__(256) void eb_kernel(const float* __restrict__ emb)
{
    int k    = (blockIdx.x * blockDim.x + threadIdx.x) >> 5;
    int lane = threadIdx.x & 31;
    if (k >= K_CB) return;
    const float* row = emb + (size_t)k * D_DIM;
    float4 v0 = *reinterpret_cast<const float4*>(&row[lane * 8]);
    float4 v1 = *reinterpret_cast<const float4*>(&row[lane * 8 + 4]);
    float s = v0.x * v0.x + v0.y * v0.y + v0.z * v0.z + v0.w * v0.w
            + v1.x * v1.x + v1.y * v1.y + v1.z * v1.z + v1.w * v1.w;
#pragma unroll
    for (int o = 16; o > 0; o >>= 1) s += __shfl_xor_sync(0xffffffffu, s, o);
    if (lane == 0) g_b[k] = s;
    __nv_bfloat162 h[4];
    h[0] = __floats2bfloat162_rn(v0.x, v0.y);
    h[1] = __floats2bfloat162_rn(v0.z, v0.w);
    h[2] = __floats2bfloat162_rn(v1.x, v1.y);
    h[3] = __floats2bfloat162_rn(v1.z, v1.w);
    *reinterpret_cast<uint4*>(&g_Eh[(size_t)k * D_DIM + lane * 8]) =
        *reinterpret_cast<uint4*>(h);
}

// ============================================================================
// Kernel 3: g_a[m] (NUMERICS FROZEN); init g_mina.
// ============================================================================
__global__ __launch_bounds__(256) void a_kernel()
{
    int m = blockIdx.x * blockDim.x + threadIdx.x;
    if (m >= N_ROWS) return;
    const float* row = g_X + (size_t)m * D_DIM;
    float acc = 0.f;
#pragma unroll 8
    for (int d = 0; d < D_DIM; d++) {
        float v = row[d];
        acc = __fadd_rn(acc, __fmul_rn(v, v));
    }
    g_a[m] = acc;
    g_mina[m] = 0x7F800000u;   // +inf
}

// ============================================================================
// Kernel 4: SCREEN — EXACT round-8 kernel (184us, rel_err 0.0).
// ============================================================================
__device__ __forceinline__ void mma_bf16(float& d0, float& d1, float& d2, float& d3,
                                         uint32_t a0, uint32_t a1, uint32_t a2, uint32_t a3,
                                         uint32_t b0, uint32_t b1)
{
    asm volatile(
        "mma.sync.aligned.m16n8k16.row.col.f32.bf16.bf16.f32 "
        "{%0,%1,%2,%3}, {%4,%5,%6,%7}, {%8,%9}, {%0,%1,%2,%3};"
        : "+f"(d0), "+f"(d1), "+f"(d2), "+f"(d3)
        : "r"(a0), "r"(a1), "r"(a2), "r"(a3), "r"(b0), "r"(b1));
}

__device__ __forceinline__ void ldsm_x4(uint32_t& r0, uint32_t& r1,
                                        uint32_t& r2, uint32_t& r3,
                                        const __nv_bfloat16* p)
{
    uint32_t addr = (uint32_t)__cvta_generic_to_shared(p);
    asm volatile("ldmatrix.sync.aligned.m8n8.x4.shared.b16 {%0,%1,%2,%3}, [%4];"
                 : "=r"(r0), "=r"(r1), "=r"(r2), "=r"(r3) : "r"(addr));
}

__device__ __forceinline__ void cp16(uint32_t smem_addr, const void* gptr)
{
    asm volatile("cp.async.cg.shared.global [%0], [%1], 16;"
                 :: "r"(smem_addr), "l"(gptr));
}

#define PITCH 40   // 32 + 8 bf16 pad

__global__ __launch_bounds__(256) void screen_kernel(float* __restrict__ enc)
{
    __shared__ __align__(16) __nv_bfloat16 Abuf[2][128 * PITCH];
    __shared__ __align__(16) __nv_bfloat16 Bbuf[2][128 * PITCH];
    __shared__ float aS[128];
    __shared__ float bS[128];
    __shared__ unsigned rowminS[128];

    const int tid  = threadIdx.x;
    const int warp = tid >> 5;
    const int lane = tid & 31;
    const int wm   = warp >> 1;      // 0..3 -> 32 rows each
    const int wn   = warp & 1;       // 0..1 -> 64 cols each
    const int m0   = blockIdx.x * 128;
    const int j0   = blockIdx.y * 128;

    if (tid < 128) {
        aS[tid] = g_a[m0 + tid];
        bS[tid] = g_b[j0 + tid];
        rowminS[tid] = 0x7F800000u;
    }

    const int prow = tid >> 2;        // 0..63
    const int pseg = tid & 3;         // 0..3

    auto prefetch = [&](int buf, int k0) {
#pragma unroll
        for (int r = 0; r < 2; r++) {
            int row = prow + r * 64;
            uint32_t da = (uint32_t)__cvta_generic_to_shared(
                &Abuf[buf][row * PITCH + pseg * 8]);
            cp16(da, &g_Xh[(size_t)(m0 + row) * D_DIM + k0 + pseg * 8]);
            uint32_t db = (uint32_t)__cvta_generic_to_shared(
                &Bbuf[buf][row * PITCH + pseg * 8]);
            cp16(db, &g_Eh[(size_t)(j0 + row) * D_DIM + k0 + pseg * 8]);
        }
        asm volatile("cp.async.commit_group;");
    };

    float acc[2][8][4];
#pragma unroll
    for (int mt = 0; mt < 2; mt++)
#pragma unroll
        for (int nn = 0; nn < 8; nn++)
#pragma unroll
            for (int c = 0; c < 4; c++) acc[mt][nn][c] = 0.f;

    const float4 z4 = make_float4(0.f, 0.f, 0.f, 0.f);

    prefetch(0, 0);

    for (int c = 0; c < 8; c++) {            // 8 chunks of BK=32
        asm volatile("cp.async.wait_group 0;");
        __syncthreads();
        if (c < 7) prefetch((c + 1) & 1, (c + 1) * 32);

        // fused enc zero-fill: 16 columns of this CTA's 128x128 block per chunk
#pragma unroll
        for (int r = 0; r < 2; r++) {
            int i   = tid + r * 256;          // 0..511
            int row = i >> 2;                 // 0..127
            int col = c * 16 + (i & 3) * 4;
            *reinterpret_cast<float4*>(
                &enc[(size_t)(m0 + row) * K_CB + j0 + col]) = z4;
        }

        const __nv_bfloat16* Asm = Abuf[c & 1];
        const __nv_bfloat16* Bsm = Bbuf[c & 1];
#pragma unroll
        for (int ks = 0; ks < 2; ks++) {
            const int krow = ks * 16;
            uint32_t a[2][4], b[4][4];
#pragma unroll
            for (int mt = 0; mt < 2; mt++) {
                const __nv_bfloat16* p =
                    &Asm[(wm * 32 + mt * 16 + (lane & 15)) * PITCH
                         + krow + (lane >> 4) * 8];
                ldsm_x4(a[mt][0], a[mt][1], a[mt][2], a[mt][3], p);
            }
#pragma unroll
            for (int nt = 0; nt < 4; nt++) {
                int nrow = wn * 64 + nt * 16 + (lane & 7) + ((lane >> 4) << 3);
                int kcol = krow + ((lane >> 3) & 1) * 8;
                ldsm_x4(b[nt][0], b[nt][1], b[nt][2], b[nt][3],
                        &Bsm[nrow * PITCH + kcol]);
            }
#pragma unroll
            for (int mt = 0; mt < 2; mt++)
#pragma unroll
                for (int nn = 0; nn < 8; nn++)
                    mma_bf16(acc[mt][nn][0], acc[mt][nn][1],
                             acc[mt][nn][2], acc[mt][nn][3],
                             a[mt][0], a[mt][1], a[mt][2], a[mt][3],
                             b[nn >> 1][(nn & 1) * 2], b[nn >> 1][(nn & 1) * 2 + 1]);
        }
    }

    // epilogue: store s = b - 2*dot (fp16); track per-row approx-min of a+s
#pragma unroll
    for (int mt = 0; mt < 2; mt++) {
#pragma unroll
        for (int half = 0; half < 2; half++) {
            int lrow = wm * 32 + mt * 16 + half * 8 + (lane >> 2);
            int grow = m0 + lrow;
            float av = aS[lrow];
            float dmin = 3.4e38f;
#pragma unroll
            for (int nn = 0; nn < 8; nn++) {
                int lcol = wn * 64 + nn * 8 + (lane & 3) * 2;
                float s0 = bS[lcol]     - 2.f * acc[mt][nn][half * 2 + 0];
                float s1 = bS[lcol + 1] - 2.f * acc[mt][nn][half * 2 + 1];
                __half2 h = __floats2half2_rn(s0, s1);
                *reinterpret_cast<__half2*>(&g_Sh[(size_t)grow * K_CB + j0 + lcol]) = h;
                dmin = fminf(dmin, fminf(av + s0, av + s1));
            }
            dmin = fminf(dmin, __shfl_xor_sync(0xffffffffu, dmin, 1));
            dmin = fminf(dmin, __shfl_xor_sync(0xffffffffu, dmin, 2));
            if ((lane & 3) == 0)
                atomicMin(&rowminS[lrow], __float_as_uint(dmin));
        }
    }
    __syncthreads();
    if (tid < 128) atomicMin(&g_mina[m0 + tid], rowminS[tid]);
}

// ============================================================================
// Kernel 5: SELECT — EXACT round-8 kernel (128 threads).
// ============================================================================
__global__ __launch_bounds__(128) void select_kernel(
    const float* __restrict__ emb,
    float* __restrict__ quant, float* __restrict__ idxout,
    float* __restrict__ enc)
{
    __shared__ float uS[D_DIM];
    __shared__ int   cand[1024];
    __shared__ int   ncand;
    __shared__ unsigned long long best;
    __shared__ int   winner;

    const int m    = blockIdx.x;
    const int tid  = threadIdx.x;
    const int lane = tid & 31;
    const int warp = tid >> 5;

    if (tid == 0) { ncand = 0; best = 0ull; }
    {
        float2 v = *reinterpret_cast<const float2*>(&g_X[(size_t)m * D_DIM + tid * 2]);
        uS[tid * 2]     = v.x;
        uS[tid * 2 + 1] = v.y;
    }
    const float a   = g_a[m];
    const float thr = __uint_as_float(g_mina[m]) + MARGIN;
    __syncthreads();

    const __half* srow = &g_Sh[(size_t)m * K_CB];
#pragma unroll
    for (int base = 0; base < K_CB; base += 1024) {
        int idx = base + tid * 8;
        uint4 raw = *reinterpret_cast<const uint4*>(&srow[idx]);
        const uint32_t rw[4] = {raw.x, raw.y, raw.z, raw.w};
#pragma unroll
        for (int q = 0; q < 4; q++) {
            __half2 h = *reinterpret_cast<const __half2*>(&rw[q]);
            float2 s2 = __half22float2(h);
            float d0 = a + s2.x, d1 = a + s2.y;
            if (d0 <= thr) { int p = atomicAdd(&ncand, 1); if (p < 1024) cand[p] = idx + q * 2; }
            if (d1 <= thr) { int p = atomicAdd(&ncand, 1); if (p < 1024) cand[p] = idx + q * 2 + 1; }
        }
    }
    __syncthreads();

    const int nc = min(ncand, 1024);
    for (int ci = warp; ci < nc; ci += 4) {
        int k = cand[ci];
        const float* e = emb + (size_t)k * D_DIM;
        float4 u0 = *reinterpret_cast<const float4*>(&uS[lane * 8]);
        float4 u1 = *reinterpret_cast<const float4*>(&uS[lane * 8 + 4]);
        float4 e0 = *reinterpret_cast<const float4*>(&e[lane * 8]);
        float4 e1 = *reinterpret_cast<const float4*>(&e[lane * 8 + 4]);
        float dot = 0.f;
        dot = fmaf(u0.x, e0.x, dot); dot = fmaf(u0.y, e0.y, dot);
        dot = fmaf(u0.z, e0.z, dot); dot = fmaf(u0.w, e0.w, dot);
        dot = fmaf(u1.x, e1.x, dot); dot = fmaf(u1.y, e1.y, dot);
        dot = fmaf(u1.z, e1.z, dot); dot = fmaf(u1.w, e1.w, dot);
#pragma unroll
        for (int o = 16; o > 0; o >>= 1)
            dot = __fadd_rn(dot, __shfl_xor_sync(0xffffffffu, dot, o));
        if (lane == 0) {
            float c  = __fmul_rn(2.0f, dot);
            float dd = __fsub_rn(__fadd_rn(a, g_b[k]), c);
            unsigned u = __float_as_uint(dd);
            unsigned s = (u & 0x80000000u) ? ~u : (u | 0x80000000u);
            unsigned long long packed =
                ((unsigned long long)(~s) << 32) | (unsigned)(~(unsigned)k);
            atomicMax(&best, packed);
        }
    }
    __syncthreads();
    if (tid == 0) {
        int k = (int)(~(unsigned)(best & 0xffffffffull));
        winner = k;
        idxout[m] = (float)k;
        enc[(size_t)m * K_CB + k] = 1.0f;
    }
    __syncthreads();
    const int k = winner;
    if (tid < 64) {
        *reinterpret_cast<float4*>(&quant[(size_t)m * D_DIM + tid * 4]) =
            *reinterpret_cast<const float4*>(&emb[(size_t)k * D_DIM + tid * 4]);
    }
}

// ============================================================================
extern "C" void kernel_launch(void* const* d_in, const int* in_sizes, int n_in,
                              void* d_out, int out_size)
{
    const float* F     = (const float*)d_in[0];
    const float* Wp    = (const float*)d_in[1];
    const float* bp    = (const float*)d_in[2];
    const float* gamma = (const float*)d_in[3];
    const float* beta  = (const float*)d_in[4];
    const float* emb   = (const float*)d_in[5];

    float* out    = (float*)d_out;
    float* quant  = out;
    float* idxout = out + (size_t)N_ROWS * D_DIM;
    float* enc    = idxout + N_ROWS;

    proj_ln_kernel<<<N_ROWS / 64, 256>>>(F, Wp, bp, gamma, beta);
    eb_kernel<<<(K_CB * 32) / 256, 256>>>(emb);
    a_kernel<<<N_ROWS / 256, 256>>>();
    screen_kernel<<<dim3(N_ROWS / 128, K_CB / 128), 256>>>(enc);
    select_kernel<<<N_ROWS, 128>>>(emb, quant, idxout, enc);
}

// round 15
// speedup vs baseline: 1.5036x; 1.0042x over previous
#include <cuda_runtime.h>
#include <cuda_bf16.h>
#include <cuda_fp16.h>
#include <cstdint>

#define N_ROWS 16384
#define H_DIM  512
#define D_DIM  256
#define K_CB   4096
#define MARGIN 1.5e-3f

// -------- scratch (static device arrays; no cudaMalloc allowed) --------
__device__ float          g_X [N_ROWS * D_DIM];     // post-LN activations (fp32)
__device__ __nv_bfloat16  g_Xh[N_ROWS * D_DIM];     // bf16 copy for screen
__device__ __nv_bfloat16  g_Eh[K_CB   * D_DIM];     // bf16 codebook
__device__ float          g_a [N_ROWS];             // fl(sum u^2) per row
__device__ float          g_b [K_CB];               // ||e_k||^2
__device__ unsigned       g_mina[N_ROWS];           // approx row-min d (float bits)
__device__ __half         g_Sh[(size_t)N_ROWS * K_CB]; // s = b - 2*dot (fp16)

// ============================================================================
// Kernel 1: projection GEMM + bias + LayerNorm (fused). v2 pipeline (banked
// round-14 WIN). FMA order unchanged -> bit-identical g_X / g_Xh.
// ============================================================================
__global__ __launch_bounds__(256, 2) void proj_ln_kernel(
    const float* __restrict__ F, const float* __restrict__ Wp,
    const float* __restrict__ bp, const float* __restrict__ gamma,
    const float* __restrict__ beta)
{
    __shared__ float As[2][16][68];    // [buf][k][m], padded
    __shared__ float Bs[2][16][260];   // [buf][k][d], padded

    const int tid  = threadIdx.x;
    const int warp = tid >> 5;
    const int lane = tid & 31;
    const int m0   = blockIdx.x * 64;

    const int arow = tid >> 2;            // 0..63
    const int akk  = (tid & 3) * 4;       // 0,4,8,12

    float acc[8][8];
#pragma unroll
    for (int i = 0; i < 8; i++)
#pragma unroll
        for (int j = 0; j < 8; j++) acc[i][j] = 0.f;

    {
        float4 v = *reinterpret_cast<const float4*>(
            &F[(size_t)(m0 + arow) * H_DIM + akk]);
        As[0][akk + 0][arow] = v.x; As[0][akk + 1][arow] = v.y;
        As[0][akk + 2][arow] = v.z; As[0][akk + 3][arow] = v.w;
#pragma unroll
        for (int r = 0; r < 4; r++) {
            int idx = tid + r * 256;
            int d  = idx >> 2;
            int kk = (idx & 3) * 4;
            float4 w = *reinterpret_cast<const float4*>(
                &Wp[(size_t)d * H_DIM + kk]);
            Bs[0][kk + 0][d] = w.x; Bs[0][kk + 1][d] = w.y;
            Bs[0][kk + 2][d] = w.z; Bs[0][kk + 3][d] = w.w;
        }
    }
    __syncthreads();

    for (int c = 0; c < 32; c++) {        // 32 chunks of BK=16
        const int cur = c & 1;
        const int nxt = cur ^ 1;
        float4 pa;
        float4 pb0, pb1, pb2, pb3;
        if (c < 31) {
            const int k0 = (c + 1) * 16;
            pa = *reinterpret_cast<const float4*>(
                &F[(size_t)(m0 + arow) * H_DIM + k0 + akk]);
            {
                int idx = tid;
                pb0 = *reinterpret_cast<const float4*>(
                    &Wp[(size_t)(idx >> 2) * H_DIM + k0 + (idx & 3) * 4]);
                idx = tid + 256;
                pb1 = *reinterpret_cast<const float4*>(
                    &Wp[(size_t)(idx >> 2) * H_DIM + k0 + (idx & 3) * 4]);
                idx = tid + 512;
                pb2 = *reinterpret_cast<const float4*>(
                    &Wp[(size_t)(idx >> 2) * H_DIM + k0 + (idx & 3) * 4]);
                idx = tid + 768;
                pb3 = *reinterpret_cast<const float4*>(
                    &Wp[(size_t)(idx >> 2) * H_DIM + k0 + (idx & 3) * 4]);
            }
        }
#pragma unroll
        for (int k = 0; k < 16; k++) {
            float4 a0 = *reinterpret_cast<const float4*>(&As[cur][k][warp * 8]);
            float4 a1 = *reinterpret_cast<const float4*>(&As[cur][k][warp * 8 + 4]);
            float4 b0 = *reinterpret_cast<const float4*>(&Bs[cur][k][lane * 8]);
            float4 b1 = *reinterpret_cast<const float4*>(&Bs[cur][k][lane * 8 + 4]);
            float a[8] = {a0.x, a0.y, a0.z, a0.w, a1.x, a1.y, a1.z, a1.w};
            float b[8] = {b0.x, b0.y, b0.z, b0.w, b1.x, b1.y, b1.z, b1.w};
#pragma unroll
            for (int i = 0; i < 8; i++)
#pragma unroll
                for (int j = 0; j < 8; j++) acc[i][j] = fmaf(a[i], b[j], acc[i][j]);
        }
        if (c < 31) {
            As[nxt][akk + 0][arow] = pa.x; As[nxt][akk + 1][arow] = pa.y;
            As[nxt][akk + 2][arow] = pa.z; As[nxt][akk + 3][arow] = pa.w;
            {
                int idx = tid;
                Bs[nxt][(idx & 3) * 4 + 0][idx >> 2] = pb0.x;
                Bs[nxt][(idx & 3) * 4 + 1][idx >> 2] = pb0.y;
                Bs[nxt][(idx & 3) * 4 + 2][idx >> 2] = pb0.z;
                Bs[nxt][(idx & 3) * 4 + 3][idx >> 2] = pb0.w;
                idx = tid + 256;
                Bs[nxt][(idx & 3) * 4 + 0][idx >> 2] = pb1.x;
                Bs[nxt][(idx & 3) * 4 + 1][idx >> 2] = pb1.y;
                Bs[nxt][(idx & 3) * 4 + 2][idx >> 2] = pb1.z;
                Bs[nxt][(idx & 3) * 4 + 3][idx >> 2] = pb1.w;
                idx = tid + 512;
                Bs[nxt][(idx & 3) * 4 + 0][idx >> 2] = pb2.x;
                Bs[nxt][(idx & 3) * 4 + 1][idx >> 2] = pb2.y;
                Bs[nxt][(idx & 3) * 4 + 2][idx >> 2] = pb2.z;
                Bs[nxt][(idx & 3) * 4 + 3][idx >> 2] = pb2.w;
                idx = tid + 768;
                Bs[nxt][(idx & 3) * 4 + 0][idx >> 2] = pb3.x;
                Bs[nxt][(idx & 3) * 4 + 1][idx >> 2] = pb3.y;
                Bs[nxt][(idx & 3) * 4 + 2][idx >> 2] = pb3.z;
                Bs[nxt][(idx & 3) * 4 + 3][idx >> 2] = pb3.w;
            }
        }
        __syncthreads();
    }

    // epilogue: +bp, LayerNorm, write g_X / g_Xh (FROZEN)
    float bpv[8], gv[8], bv[8];
#pragma unroll
    for (int j = 0; j < 8; j++) {
        int d = lane * 8 + j;
        bpv[j] = bp[d]; gv[j] = gamma[d]; bv[j] = beta[d];
    }
#pragma unroll
    for (int i = 0; i < 8; i++) {
#pragma unroll
        for (int j = 0; j < 8; j++) acc[i][j] += bpv[j];
        float s = 0.f;
#pragma unroll
        for (int j = 0; j < 8; j++) s += acc[i][j];
#pragma unroll
        for (int o = 16; o > 0; o >>= 1) s += __shfl_xor_sync(0xffffffffu, s, o);
        float mu = s * (1.f / 256.f);
        float ss = 0.f;
#pragma unroll
        for (int j = 0; j < 8; j++) { float d2 = acc[i][j] - mu; ss += d2 * d2; }
#pragma unroll
        for (int o = 16; o > 0; o >>= 1) ss += __shfl_xor_sync(0xffffffffu, ss, o);
        float var = ss * (1.f / 256.f);
        float rs  = rsqrtf(var + 1e-5f);
        int row = m0 + warp * 8 + i;
        float out[8];
#pragma unroll
        for (int j = 0; j < 8; j++)
            out[j] = (acc[i][j] - mu) * rs * gv[j] + bv[j];
        *reinterpret_cast<float4*>(&g_X[(size_t)row * D_DIM + lane * 8]) =
            make_float4(out[0], out[1], out[2], out[3]);
        *reinterpret_cast<float4*>(&g_X[(size_t)row * D_DIM + lane * 8 + 4]) =
            make_float4(out[4], out[5], out[6], out[7]);
        __nv_bfloat162 h[4];
        h[0] = __floats2bfloat162_rn(out[0], out[1]);
        h[1] = __floats2bfloat162_rn(out[2], out[3]);
        h[2] = __floats2bfloat162_rn(out[4], out[5]);
        h[3] = __floats2bfloat162_rn(out[6], out[7]);
        *reinterpret_cast<uint4*>(&g_Xh[(size_t)row * D_DIM + lane * 8]) =
            *reinterpret_cast<uint4*>(h);
    }
}

// ============================================================================
// Kernel 2: per-code ||e||^2 + bf16 conversion.
// ============================================================================
__global__ __launch_bounds__(256) void eb_kernel(const float* __restrict__ emb)
{
    int k    = (blockIdx.x * blockDim.x + threadIdx.x) >> 5;
    int lane = threadIdx.x & 31;
    if (k >= K_CB) return;
    const float* row = emb + (size_t)k * D_DIM;
    float4 v0 = *reinterpret_cast<const float4*>(&row[lane * 8]);
    float4 v1 = *reinterpret_cast<const float4*>(&row[lane * 8 + 4]);
    float s = v0.x * v0.x + v0.y * v0.y + v0.z * v0.z + v0.w * v0.w
            + v1.x * v1.x + v1.y * v1.y + v1.z * v1.z + v1.w * v1.w;
#pragma unroll
    for (int o = 16; o > 0; o >>= 1) s += __shfl_xor_sync(0xffffffffu, s, o);
    if (lane == 0) g_b[k] = s;
    __nv_bfloat162 h[4];
    h[0] = __floats2bfloat162_rn(v0.x, v0.y);
    h[1] = __floats2bfloat162_rn(v0.z, v0.w);
    h[2] = __floats2bfloat162_rn(v1.x, v1.y);
    h[3] = __floats2bfloat162_rn(v1.z, v1.w);
    *reinterpret_cast<uint4*>(&g_Eh[(size_t)k * D_DIM + lane * 8]) =
        *reinterpret_cast<uint4*>(h);
}

// ============================================================================
// Kernel 3: g_a[m] (NUMERICS FROZEN); init g_mina.
// ============================================================================
__global__ __launch_bounds__(256) void a_kernel()
{
    int m = blockIdx.x * blockDim.x + threadIdx.x;
    if (m >= N_ROWS) return;
    const float* row = g_X + (size_t)m * D_DIM;
    float acc = 0.f;
#pragma unroll 8
    for (int d = 0; d < D_DIM; d++) {
        float v = row[d];
        acc = __fadd_rn(acc, __fmul_rn(v, v));
    }
    g_a[m] = acc;
    g_mina[m] = 0x7F800000u;   // +inf
}

// ============================================================================
// Kernel 4: SCREEN — EXACT round-8 kernel (185us, rel_err 0.0). UNTOUCHED.
// ============================================================================
__device__ __forceinline__ void mma_bf16(float& d0, float& d1, float& d2, float& d3,
                                         uint32_t a0, uint32_t a1, uint32_t a2, uint32_t a3,
                                         uint32_t b0, uint32_t b1)
{
    asm volatile(
        "mma.sync.aligned.m16n8k16.row.col.f32.bf16.bf16.f32 "
        "{%0,%1,%2,%3}, {%4,%5,%6,%7}, {%8,%9}, {%0,%1,%2,%3};"
        : "+f"(d0), "+f"(d1), "+f"(d2), "+f"(d3)
        : "r"(a0), "r"(a1), "r"(a2), "r"(a3), "r"(b0), "r"(b1));
}

__device__ __forceinline__ void ldsm_x4(uint32_t& r0, uint32_t& r1,
                                        uint32_t& r2, uint32_t& r3,
                                        const __nv_bfloat16* p)
{
    uint32_t addr = (uint32_t)__cvta_generic_to_shared(p);
    asm volatile("ldmatrix.sync.aligned.m8n8.x4.shared.b16 {%0,%1,%2,%3}, [%4];"
                 : "=r"(r0), "=r"(r1), "=r"(r2), "=r"(r3) : "r"(addr));
}

__device__ __forceinline__ void cp16(uint32_t smem_addr, const void* gptr)
{
    asm volatile("cp.async.cg.shared.global [%0], [%1], 16;"
                 :: "r"(smem_addr), "l"(gptr));
}

#define PITCH 40   // 32 + 8 bf16 pad

__global__ __launch_bounds__(256) void screen_kernel(float* __restrict__ enc)
{
    __shared__ __align__(16) __nv_bfloat16 Abuf[2][128 * PITCH];
    __shared__ __align__(16) __nv_bfloat16 Bbuf[2][128 * PITCH];
    __shared__ float aS[128];
    __shared__ float bS[128];
    __shared__ unsigned rowminS[128];

    const int tid  = threadIdx.x;
    const int warp = tid >> 5;
    const int lane = tid & 31;
    const int wm   = warp >> 1;      // 0..3 -> 32 rows each
    const int wn   = warp & 1;       // 0..1 -> 64 cols each
    const int m0   = blockIdx.x * 128;
    const int j0   = blockIdx.y * 128;

    if (tid < 128) {
        aS[tid] = g_a[m0 + tid];
        bS[tid] = g_b[j0 + tid];
        rowminS[tid] = 0x7F800000u;
    }

    const int prow = tid >> 2;        // 0..63
    const int pseg = tid & 3;         // 0..3

    auto prefetch = [&](int buf, int k0) {
#pragma unroll
        for (int r = 0; r < 2; r++) {
            int row = prow + r * 64;
            uint32_t da = (uint32_t)__cvta_generic_to_shared(
                &Abuf[buf][row * PITCH + pseg * 8]);
            cp16(da, &g_Xh[(size_t)(m0 + row) * D_DIM + k0 + pseg * 8]);
            uint32_t db = (uint32_t)__cvta_generic_to_shared(
                &Bbuf[buf][row * PITCH + pseg * 8]);
            cp16(db, &g_Eh[(size_t)(j0 + row) * D_DIM + k0 + pseg * 8]);
        }
        asm volatile("cp.async.commit_group;");
    };

    float acc[2][8][4];
#pragma unroll
    for (int mt = 0; mt < 2; mt++)
#pragma unroll
        for (int nn = 0; nn < 8; nn++)
#pragma unroll
            for (int c = 0; c < 4; c++) acc[mt][nn][c] = 0.f;

    const float4 z4 = make_float4(0.f, 0.f, 0.f, 0.f);

    prefetch(0, 0);

    for (int c = 0; c < 8; c++) {            // 8 chunks of BK=32
        asm volatile("cp.async.wait_group 0;");
        __syncthreads();
        if (c < 7) prefetch((c + 1) & 1, (c + 1) * 32);

        // fused enc zero-fill: 16 columns of this CTA's 128x128 block per chunk
#pragma unroll
        for (int r = 0; r < 2; r++) {
            int i   = tid + r * 256;          // 0..511
            int row = i >> 2;                 // 0..127
            int col = c * 16 + (i & 3) * 4;
            *reinterpret_cast<float4*>(
                &enc[(size_t)(m0 + row) * K_CB + j0 + col]) = z4;
        }

        const __nv_bfloat16* Asm = Abuf[c & 1];
        const __nv_bfloat16* Bsm = Bbuf[c & 1];
#pragma unroll
        for (int ks = 0; ks < 2; ks++) {
            const int krow = ks * 16;
            uint32_t a[2][4], b[4][4];
#pragma unroll
            for (int mt = 0; mt < 2; mt++) {
                const __nv_bfloat16* p =
                    &Asm[(wm * 32 + mt * 16 + (lane & 15)) * PITCH
                         + krow + (lane >> 4) * 8];
                ldsm_x4(a[mt][0], a[mt][1], a[mt][2], a[mt][3], p);
            }
#pragma unroll
            for (int nt = 0; nt < 4; nt++) {
                int nrow = wn * 64 + nt * 16 + (lane & 7) + ((lane >> 4) << 3);
                int kcol = krow + ((lane >> 3) & 1) * 8;
                ldsm_x4(b[nt][0], b[nt][1], b[nt][2], b[nt][3],
                        &Bsm[nrow * PITCH + kcol]);
            }
#pragma unroll
            for (int mt = 0; mt < 2; mt++)
#pragma unroll
                for (int nn = 0; nn < 8; nn++)
                    mma_bf16(acc[mt][nn][0], acc[mt][nn][1],
                             acc[mt][nn][2], acc[mt][nn][3],
                             a[mt][0], a[mt][1], a[mt][2], a[mt][3],
                             b[nn >> 1][(nn & 1) * 2], b[nn >> 1][(nn & 1) * 2 + 1]);
        }
    }

    // epilogue: store s = b - 2*dot (fp16); track per-row approx-min of a+s
#pragma unroll
    for (int mt = 0; mt < 2; mt++) {
#pragma unroll
        for (int half = 0; half < 2; half++) {
            int lrow = wm * 32 + mt * 16 + half * 8 + (lane >> 2);
            int grow = m0 + lrow;
            float av = aS[lrow];
            float dmin = 3.4e38f;
#pragma unroll
            for (int nn = 0; nn < 8; nn++) {
                int lcol = wn * 64 + nn * 8 + (lane & 3) * 2;
                float s0 = bS[lcol]     - 2.f * acc[mt][nn][half * 2 + 0];
                float s1 = bS[lcol + 1] - 2.f * acc[mt][nn][half * 2 + 1];
                __half2 h = __floats2half2_rn(s0, s1);
                *reinterpret_cast<__half2*>(&g_Sh[(size_t)grow * K_CB + j0 + lcol]) = h;
                dmin = fminf(dmin, fminf(av + s0, av + s1));
            }
            dmin = fminf(dmin, __shfl_xor_sync(0xffffffffu, dmin, 1));
            dmin = fminf(dmin, __shfl_xor_sync(0xffffffffu, dmin, 2));
            if ((lane & 3) == 0)
                atomicMin(&rowminS[lrow], __float_as_uint(dmin));
        }
    }
    __syncthreads();
    if (tid < 128) atomicMin(&g_mina[m0 + tid], rowminS[tid]);
}

// ============================================================================
// Kernel 5: SELECT v3 — scan with batched loads, MARGIN tightened to 1.5e-3
// (>=3x the 4.6e-4 screen+fp16 error bound), rescore software-pipelined.
// Per-candidate dot computation is BIT-IDENTICAL to the validated kernel.
// ============================================================================
__global__ __launch_bounds__(128) void select_kernel(
    const float* __restrict__ emb,
    float* __restrict__ quant, float* __restrict__ idxout,
    float* __restrict__ enc)
{
    __shared__ float uS[D_DIM];
    __shared__ int   cand[1024];
    __shared__ int   ncand;
    __shared__ unsigned long long best;
    __shared__ int   winner;

    const int m    = blockIdx.x;
    const int tid  = threadIdx.x;
    const int lane = tid & 31;
    const int warp = tid >> 5;

    if (tid == 0) { ncand = 0; best = 0ull; }
    {
        float2 v = *reinterpret_cast<const float2*>(&g_X[(size_t)m * D_DIM + tid * 2]);
        uS[tid * 2]     = v.x;
        uS[tid * 2 + 1] = v.y;
    }
    const float a   = g_a[m];
    const float thr = __uint_as_float(g_mina[m]) + MARGIN;
    __syncthreads();

    // scan: batch all 4 uint4 loads (MLP=4), then filter
    const __half* srow = &g_Sh[(size_t)m * K_CB];
    uint4 raw[4];
#pragma unroll
    for (int r = 0; r < 4; r++)
        raw[r] = *reinterpret_cast<const uint4*>(&srow[r * 1024 + tid * 8]);
#pragma unroll
    for (int r = 0; r < 4; r++) {
        int idx = r * 1024 + tid * 8;
        const uint32_t rw[4] = {raw[r].x, raw[r].y, raw[r].z, raw[r].w};
#pragma unroll
        for (int q = 0; q < 4; q++) {
            __half2 h = *reinterpret_cast<const __half2*>(&rw[q]);
            float2 s2 = __half22float2(h);
            float d0 = a + s2.x, d1 = a + s2.y;
            if (d0 <= thr) { int p = atomicAdd(&ncand, 1); if (p < 1024) cand[p] = idx + q * 2; }
            if (d1 <= thr) { int p = atomicAdd(&ncand, 1); if (p < 1024) cand[p] = idx + q * 2 + 1; }
        }
    }
    __syncthreads();

    const int nc = min(ncand, 1024);
    // rescore, software-pipelined across candidates (per-candidate math frozen)
    {
        float4 u0 = *reinterpret_cast<const float4*>(&uS[lane * 8]);
        float4 u1 = *reinterpret_cast<const float4*>(&uS[lane * 8 + 4]);
        int ci = warp;
        int curk = 0;
        float4 e0, e1;
        if (ci < nc) {
            curk = cand[ci];
            const float* e = emb + (size_t)curk * D_DIM;
            e0 = *reinterpret_cast<const float4*>(&e[lane * 8]);
            e1 = *reinterpret_cast<const float4*>(&e[lane * 8 + 4]);
        }
        while (ci < nc) {
            int cj = ci + 4;
            int nk = 0;
            float4 f0, f1;
            if (cj < nc) {                    // prefetch next candidate row
                nk = cand[cj];
                const float* e = emb + (size_t)nk * D_DIM;
                f0 = *reinterpret_cast<const float4*>(&e[lane * 8]);
                f1 = *reinterpret_cast<const float4*>(&e[lane * 8 + 4]);
            }
            // frozen dot: same fmaf chain + xor-tree __fadd_rn reduce
            float dot = 0.f;
            dot = fmaf(u0.x, e0.x, dot); dot = fmaf(u0.y, e0.y, dot);
            dot = fmaf(u0.z, e0.z, dot); dot = fmaf(u0.w, e0.w, dot);
            dot = fmaf(u1.x, e1.x, dot); dot = fmaf(u1.y, e1.y, dot);
            dot = fmaf(u1.z, e1.z, dot); dot = fmaf(u1.w, e1.w, dot);
#pragma unroll
            for (int o = 16; o > 0; o >>= 1)
                dot = __fadd_rn(dot, __shfl_xor_sync(0xffffffffu, dot, o));
            if (lane == 0) {
                float c  = __fmul_rn(2.0f, dot);
                float dd = __fsub_rn(__fadd_rn(a, g_b[curk]), c);
                unsigned u = __float_as_uint(dd);
                unsigned s = (u & 0x80000000u) ? ~u : (u | 0x80000000u);
                unsigned long long packed =
                    ((unsigned long long)(~s) << 32) | (unsigned)(~(unsigned)curk);
                atomicMax(&best, packed);
            }
            ci = cj; curk = nk; e0 = f0; e1 = f1;
        }
    }
    __syncthreads();
    if (tid == 0) {
        int k = (int)(~(unsigned)(best & 0xffffffffull));
        winner = k;
        idxout[m] = (float)k;
        enc[(size_t)m * K_CB + k] = 1.0f;
    }
    __syncthreads();
    const int k = winner;
    if (tid < 64) {
        *reinterpret_cast<float4*>(&quant[(size_t)m * D_DIM + tid * 4]) =
            *reinterpret_cast<const float4*>(&emb[(size_t)k * D_DIM + tid * 4]);
    }
}

// ============================================================================
extern "C" void kernel_launch(void* const* d_in, const int* in_sizes, int n_in,
                              void* d_out, int out_size)
{
    const float* F     = (const float*)d_in[0];
    const float* Wp    = (const float*)d_in[1];
    const float* bp    = (const float*)d_in[2];
    const float* gamma = (const float*)d_in[3];
    const float* beta  = (const float*)d_in[4];
    const float* emb   = (const float*)d_in[5];

    float* out    = (float*)d_out;
    float* quant  = out;
    float* idxout = out + (size_t)N_ROWS * D_DIM;
    float* enc    = idxout + N_ROWS;

    proj_ln_kernel<<<N_ROWS / 64, 256>>>(F, Wp, bp, gamma, beta);
    eb_kernel<<<(K_CB * 32) / 256, 256>>>(emb);
    a_kernel<<<N_ROWS / 256, 256>>>();
    screen_kernel<<<dim3(N_ROWS / 128, K_CB / 128), 256>>>(enc);
    select_kernel<<<N_ROWS, 128>>>(emb, quant, idxout, enc);
}